// round 7
// baseline (speedup 1.0000x reference)
#include <cuda_runtime.h>
#include <cstdint>

// Gather-and-concat:
//   out[b, 0:512]    = lstm1[b, input_length[b]-1, :]
//   out[b, 512:1024] = lstm2[b, support_length[b]-1, :]
// B=64, T=2048, H=512, fp32. Lengths arrive as int32 (JAX silently downcasts
// the reference's int64 without x64 mode).
//
// At the launch-overhead floor: traffic 512 KB (<1% HBM), body is the
// irreducible chain len-LDG -> gather-LDG -> STG. This round probes CTA
// count: 32 CTAs x 512 threads, 2 batches per CTA (threads [0,256) -> batch
// 2*blockIdx, [256,512) -> batch 2*blockIdx+1; within each batch, low 128
// threads copy the lstm1 half, high 128 the lstm2 half). One float4/thread,
// single wave, 32-bit indexing throughout.

static constexpr int B = 64;
static constexpr int T = 2048;
static constexpr int H = 512;

__global__ __launch_bounds__(512, 1)
void vlos_gather_kernel(const float4* __restrict__ lstm1,
                        const float4* __restrict__ lstm2,
                        const int* __restrict__ input_length,
                        const int* __restrict__ support_length,
                        float4* __restrict__ out)
{
    const int t   = threadIdx.x;               // 0..511
    const int b   = blockIdx.x * 2 + (t >> 8); // batch 0..63
    const int src = (t >> 7) & 1;              // 0 = lstm1 half, 1 = lstm2 half
    const int col = t & 127;                   // float4 column within the row

    // Uniform per-(batch,half) length load (warp-broadcast).
    int row = __ldg(src ? &support_length[b] : &input_length[b]) - 1;
    row = max(0, min(T - 1, row));             // defensive clamp

    const float4* base = src ? lstm2 : lstm1;
    // 32-bit offsets: (b*T + row) * 128 <= 16.7M float4s, fits int.
    const int src_off = (b * T + row) * (H / 4) + col;
    const int dst_off = b * (2 * H / 4) + src * (H / 4) + col;

    out[dst_off] = __ldg(&base[src_off]);
}

extern "C" void kernel_launch(void* const* d_in, const int* in_sizes, int n_in,
                              void* d_out, int out_size)
{
    const float4* lstm1 = (const float4*)d_in[0];
    const float4* lstm2 = (const float4*)d_in[1];
    const int*    ilen  = (const int*)d_in[2];
    const int*    slen  = (const int*)d_in[3];
    float4*       out   = (float4*)d_out;

    vlos_gather_kernel<<<B / 2, 512>>>(lstm1, lstm2, ilen, slen, out);
}

// round 8
// speedup vs baseline: 1.0141x; 1.0141x over previous
#include <cuda_runtime.h>
#include <cstdint>

// Gather-and-concat (FINAL — converged at the launch-overhead floor):
//   out[b, 0:512]    = lstm1[b, input_length[b]-1, :]
//   out[b, 512:1024] = lstm2[b, support_length[b]-1, :]
// B=64, T=2048, H=512, fp32. Lengths arrive as int32 (JAX silently downcasts
// the reference's int64 without x64 mode).
//
// Why this is the floor (measured over R4-R7):
//   - traffic 512 KB total = <1% of HBM; DRAM/L2/L1 all <1% busy in ncu
//   - body = irreducible 2-access dependent chain (len-LDG -> gather-LDG -> STG);
//     both legs are L2-resident across graph replays (~250 cyc each)
//   - remaining ~4 us is fixed graph-replay launch/teardown; grid-shape probes
//     (128x128 -> 6.9us, 64x256 -> 4.58us, 32x512 -> 4.61us) bracket the optimum
//
// Shape: 64 CTAs (one per batch) x 256 threads; threads 0-127 copy the lstm1
// half, 128-255 the lstm2 half; one float4 per thread; single wave; 32-bit
// indexing (max offset 16.7M float4s < 2^31).

static constexpr int B = 64;
static constexpr int T = 2048;
static constexpr int H = 512;

__global__ __launch_bounds__(256, 1)
void vlos_gather_kernel(const float4* __restrict__ lstm1,
                        const float4* __restrict__ lstm2,
                        const int* __restrict__ input_length,
                        const int* __restrict__ support_length,
                        float4* __restrict__ out)
{
    const int b   = blockIdx.x;          // batch 0..63
    const int t   = threadIdx.x;         // 0..255
    const int src = t >> 7;              // 0 = lstm1 half, 1 = lstm2 half
    const int col = t & 127;             // float4 column within the 512-float row

    // Uniform per-half length load (warp-broadcast, single transaction).
    int row = __ldg(src ? &support_length[b] : &input_length[b]) - 1;
    row = max(0, min(T - 1, row));       // defensive: dtype surprises -> rel_err, not crash

    const float4* base = src ? lstm2 : lstm1;
    // 32-bit offsets: (b*T + row) * 128 <= 16.7M, well inside int range.
    const int src_off = (b * T + row) * (H / 4) + col;
    const int dst_off = b * (2 * H / 4) + src * (H / 4) + col;

    out[dst_off] = __ldg(&base[src_off]);
}

extern "C" void kernel_launch(void* const* d_in, const int* in_sizes, int n_in,
                              void* d_out, int out_size)
{
    const float4* lstm1 = (const float4*)d_in[0];
    const float4* lstm2 = (const float4*)d_in[1];
    const int*    ilen  = (const int*)d_in[2];
    const int*    slen  = (const int*)d_in[3];
    float4*       out   = (float4*)d_out;

    vlos_gather_kernel<<<B, 256>>>(lstm1, lstm2, ilen, slen, out);
}